// round 2
// baseline (speedup 1.0000x reference)
#include <cuda_runtime.h>
#include <math.h>

#define SQ 3072
#define DM 3072
#define NH 24
#define HD 128
#define BLKROWS 2048

// ---------------- scratch (device globals: allocation-free) ----------------
__device__ float g_q[SQ * DM];
__device__ float g_k[SQ * DM];
__device__ float g_v[SQ * DM];
__device__ float g_t[3 * 1024 * 64];

// ---------------- packed fp32x2 helpers ------------------------------------
__device__ __forceinline__ unsigned long long pk2(float lo, float hi) {
    unsigned long long r;
    asm("mov.b64 %0, {%1, %2};" : "=l"(r) : "f"(lo), "f"(hi));
    return r;
}
__device__ __forceinline__ void upk2(unsigned long long v, float& lo, float& hi) {
    asm("mov.b64 {%0, %1}, %2;" : "=f"(lo), "=f"(hi) : "l"(v));
}
__device__ __forceinline__ void fma2(unsigned long long& d, unsigned long long a, unsigned long long b) {
    asm("fma.rn.f32x2 %0, %1, %2, %0;" : "+l"(d) : "l"(a), "l"(b));
}
__device__ __forceinline__ unsigned long long mul2(unsigned long long a, unsigned long long b) {
    unsigned long long r;
    asm("mul.rn.f32x2 %0, %1, %2;" : "=l"(r) : "l"(a), "l"(b));
    return r;
}

// ---------------- 1) QKV GEMM: C = h @ W.T + b -----------------------------
__global__ __launch_bounds__(256, 2) void qkv_gemm_kernel(
    const float* __restrict__ A,
    const float* __restrict__ Wq, const float* __restrict__ Wk, const float* __restrict__ Wv,
    const float* __restrict__ bq, const float* __restrict__ bk, const float* __restrict__ bv)
{
    const int z = blockIdx.z;
    const float* __restrict__ W    = (z == 0) ? Wq : (z == 1) ? Wk : Wv;
    const float* __restrict__ bias = (z == 0) ? bq : (z == 1) ? bk : bv;
    float* C = (z == 0) ? g_q : (z == 1) ? g_k : g_v;

    __shared__ float As[8][128];
    __shared__ float Bs[8][128];

    const int tid  = threadIdx.x;
    const int m0   = blockIdx.y * 128;
    const int n0   = blockIdx.x * 128;
    const int lrow = tid >> 1;
    const int lc   = (tid & 1) * 4;
    const int ty   = tid >> 4;
    const int tx   = tid & 15;

    unsigned long long acc[8][4];
#pragma unroll
    for (int i = 0; i < 8; i++)
#pragma unroll
        for (int j = 0; j < 4; j++) acc[i][j] = 0ull;

    const float* Aptr = A + (size_t)(m0 + lrow) * DM + lc;
    const float* Wptr = W + (size_t)(n0 + lrow) * DM + lc;

    for (int k0 = 0; k0 < DM; k0 += 8) {
        float4 av = *(const float4*)(Aptr + k0);
        float4 wv = *(const float4*)(Wptr + k0);
        As[lc + 0][lrow] = av.x; As[lc + 1][lrow] = av.y;
        As[lc + 2][lrow] = av.z; As[lc + 3][lrow] = av.w;
        Bs[lc + 0][lrow] = wv.x; Bs[lc + 1][lrow] = wv.y;
        Bs[lc + 2][lrow] = wv.z; Bs[lc + 3][lrow] = wv.w;
        __syncthreads();
#pragma unroll
        for (int kk = 0; kk < 8; kk++) {
            float ar[8];
            *(float4*)&ar[0] = *(const float4*)&As[kk][ty * 8];
            *(float4*)&ar[4] = *(const float4*)&As[kk][ty * 8 + 4];
            ulonglong2 b0 = *(const ulonglong2*)&Bs[kk][tx * 8];
            ulonglong2 b1 = *(const ulonglong2*)&Bs[kk][tx * 8 + 4];
#pragma unroll
            for (int i = 0; i < 8; i++) {
                unsigned long long a2 = pk2(ar[i], ar[i]);
                fma2(acc[i][0], a2, b0.x);
                fma2(acc[i][1], a2, b0.y);
                fma2(acc[i][2], a2, b1.x);
                fma2(acc[i][3], a2, b1.y);
            }
        }
        __syncthreads();
    }

    float bb[8];
#pragma unroll
    for (int j = 0; j < 8; j++) bb[j] = bias[n0 + tx * 8 + j];
#pragma unroll
    for (int i = 0; i < 8; i++) {
        float c[8];
#pragma unroll
        for (int j = 0; j < 4; j++) upk2(acc[i][j], c[2 * j], c[2 * j + 1]);
#pragma unroll
        for (int j = 0; j < 8; j++) c[j] += bb[j];
        float* dst = C + (size_t)(m0 + ty * 8 + i) * DM + n0 + tx * 8;
        *(float4*)dst       = make_float4(c[0], c[1], c[2], c[3]);
        *(float4*)(dst + 4) = make_float4(c[4], c[5], c[6], c[7]);
    }
}

// ---------------- 2) LoRA down: t[x] = h[2048:,:] @ down[x].T --------------
__global__ __launch_bounds__(256) void lora_down_kernel(
    const float* __restrict__ h,
    const float* __restrict__ dq, const float* __restrict__ dk, const float* __restrict__ dv)
{
    const int x = blockIdx.y;
    const float* __restrict__ D = (x == 0) ? dq : (x == 1) ? dk : dv;
    const int i0 = blockIdx.x * 32;

    __shared__ float hs[32][65];
    __shared__ float ds[64][65];

    const int tid = threadIdx.x;
    const int r   = tid & 31;
    const int c0  = (tid >> 5) * 8;

    float acc[8] = {0.f, 0.f, 0.f, 0.f, 0.f, 0.f, 0.f, 0.f};

    for (int k0 = 0; k0 < DM; k0 += 64) {
#pragma unroll
        for (int t = 0; t < 8; t++) {
            int idx = tid + t * 256;
            int rr = idx >> 6, cc = idx & 63;
            hs[rr][cc] = h[(size_t)(BLKROWS + i0 + rr) * DM + k0 + cc];
        }
#pragma unroll
        for (int t = 0; t < 16; t++) {
            int idx = tid + t * 256;
            int rr = idx >> 6, cc = idx & 63;
            ds[rr][cc] = D[(size_t)rr * DM + k0 + cc];
        }
        __syncthreads();
#pragma unroll 8
        for (int kk = 0; kk < 64; kk++) {
            float a = hs[r][kk];
#pragma unroll
            for (int j = 0; j < 8; j++) acc[j] += a * ds[c0 + j][kk];
        }
        __syncthreads();
    }
#pragma unroll
    for (int j = 0; j < 8; j++)
        g_t[x * 65536 + (i0 + r) * 64 + c0 + j] = acc[j];
}

// ---------------- 3) LoRA up: C[2048+i, n] += t @ up.T  (scale = 1) --------
__global__ __launch_bounds__(256) void lora_up_kernel(
    const float* __restrict__ uq, const float* __restrict__ uk, const float* __restrict__ uv)
{
    const int x = blockIdx.z;
    const float* __restrict__ U = (x == 0) ? uq : (x == 1) ? uk : uv;
    float* C = (x == 0) ? g_q : (x == 1) ? g_k : g_v;

    const int n0 = blockIdx.x * 64;
    const int i0 = blockIdx.y * 64;

    __shared__ float ts[64][68];  // [rank][i]
    __shared__ float us[64][68];  // [rank][n]

    const int tid = threadIdx.x;
#pragma unroll
    for (int t = 0; t < 16; t++) {
        int idx = tid + t * 256;
        int ii = idx >> 6, rr = idx & 63;
        ts[rr][ii] = g_t[x * 65536 + (i0 + ii) * 64 + rr];
        us[rr][ii] = U[(size_t)(n0 + ii) * 64 + rr];
    }
    __syncthreads();

    const int tm = tid >> 4, tn = tid & 15;
    unsigned long long acc[4][2];
#pragma unroll
    for (int i = 0; i < 4; i++) { acc[i][0] = 0ull; acc[i][1] = 0ull; }

#pragma unroll 8
    for (int rr = 0; rr < 64; rr++) {
        float4 a = *(const float4*)&ts[rr][tm * 4];
        ulonglong2 b = *(const ulonglong2*)&us[rr][tn * 4];
        float af[4] = {a.x, a.y, a.z, a.w};
#pragma unroll
        for (int i = 0; i < 4; i++) {
            unsigned long long a2 = pk2(af[i], af[i]);
            fma2(acc[i][0], a2, b.x);
            fma2(acc[i][1], a2, b.y);
        }
    }
#pragma unroll
    for (int i = 0; i < 4; i++) {
        float c0, c1, c2, c3;
        upk2(acc[i][0], c0, c1);
        upk2(acc[i][1], c2, c3);
        float* dst = C + (size_t)(BLKROWS + i0 + tm * 4 + i) * DM + n0 + tn * 4;
        float4 old = *(float4*)dst;
        old.x += c0; old.y += c1; old.z += c2; old.w += c3;
        *(float4*)dst = old;
    }
}

// ---------------- 4) RMSNorm (per head) + RoPE, in place on q/k ------------
__global__ __launch_bounds__(128) void rms_rope_kernel(
    const float* __restrict__ wq, const float* __restrict__ wk,
    const float* __restrict__ cosb, const float* __restrict__ sinb)
{
    const int s  = blockIdx.x;
    const int hh = blockIdx.y;
    const int qk = blockIdx.z;
    const int d  = threadIdx.x;

    float* buf = qk ? g_k : g_q;
    const float* w = qk ? wk : wq;

    size_t idx = (size_t)s * DM + hh * HD + d;
    float x = buf[idx];

    float v = x * x;
#pragma unroll
    for (int o = 16; o; o >>= 1) v += __shfl_xor_sync(0xffffffffu, v, o);
    __shared__ float red[4];
    if ((d & 31) == 0) red[d >> 5] = v;
    __syncthreads();
    float tot = red[0] + red[1] + red[2] + red[3];

    float y = x * rsqrtf(tot * (1.0f / 128.0f) + 1e-6f) * w[d];
    float partner = __shfl_xor_sync(0xffffffffu, y, 1);
    float xr = (d & 1) ? partner : -partner;
    buf[idx] = y * cosb[s * HD + d] + xr * sinb[s * HD + d];
}

// ---------------- 5) Flash attention (fp32, f32x2 FMAs) --------------------
// mask semantics: image rows (<2048) attend ALL 3072 cols; cond rows
// (>=2048) attend only cols [2048, 3072). Boundary is tile-aligned.
#define ATT_SMEM_FLOATS (128 * 132 + 128 * 68 + 64 * 132 + 64 * 132)
#define ATT_SMEM_BYTES  (ATT_SMEM_FLOATS * 4)

__global__ __launch_bounds__(512) void attn_kernel(float* __restrict__ out)
{
    extern __shared__ float sm[];
    float* Qs = sm;                    // [128][132]  Qs[d][m], pre-scaled
    float* Ks = Qs + 128 * 132;        // [128][68]   Ks[d][n]
    float* Vs = Ks + 128 * 68;         // [64][132]   Vs[n][d]
    float* Ps = Vs + 64 * 132;         // [64][132]   Ps[n][m]

    const int m0  = blockIdx.x * 128;
    const int h   = blockIdx.y;
    const int tid = threadIdx.x;
    const int tm  = tid >> 4;          // 0..31 -> q rows tm*4..+3
    const int tn  = tid & 15;          // S cols tn*4..+3 / O cols tn*8..+7
    const float sc = 0.08838834764831845f;  // 1/sqrt(128)

    for (int idx = tid; idx < 128 * 128; idx += 512) {
        int m = idx >> 7, d = idx & 127;
        Qs[d * 132 + m] = g_q[(size_t)(m0 + m) * DM + h * HD + d] * sc;
    }

    unsigned long long op[4][4];
#pragma unroll
    for (int i = 0; i < 4; i++)
#pragma unroll
        for (int j = 0; j < 4; j++) op[i][j] = 0ull;

    float mi[4] = {-1e30f, -1e30f, -1e30f, -1e30f};
    float li[4] = {0.f, 0.f, 0.f, 0.f};

    const int n_start = (m0 >= BLKROWS) ? BLKROWS : 0;

    for (int n0 = n_start; n0 < SQ; n0 += 64) {
        for (int idx = tid; idx < 64 * 128; idx += 512) {
            int n = idx >> 7, d = idx & 127;
            size_t g = (size_t)(n0 + n) * DM + h * HD + d;
            Ks[d * 68 + n]  = g_k[g];
            Vs[n * 132 + d] = g_v[g];
        }
        __syncthreads();

        // S = (Q*sc) K^T
        unsigned long long sp[4][2];
#pragma unroll
        for (int i = 0; i < 4; i++) { sp[i][0] = 0ull; sp[i][1] = 0ull; }
#pragma unroll 8
        for (int d = 0; d < 128; d++) {
            float4 a = *(const float4*)&Qs[d * 132 + tm * 4];
            ulonglong2 b = *(const ulonglong2*)&Ks[d * 68 + tn * 4];
            float af[4] = {a.x, a.y, a.z, a.w};
#pragma unroll
            for (int i = 0; i < 4; i++) {
                unsigned long long a2 = pk2(af[i], af[i]);
                fma2(sp[i][0], a2, b.x);
                fma2(sp[i][1], a2, b.y);
            }
        }
        float s[4][4];
#pragma unroll
        for (int i = 0; i < 4; i++) {
            upk2(sp[i][0], s[i][0], s[i][1]);
            upk2(sp[i][1], s[i][2], s[i][3]);
        }

        // online softmax; rows live on 16 consecutive lanes (same tm)
#pragma unroll
        for (int i = 0; i < 4; i++) {
            float mx = fmaxf(fmaxf(s[i][0], s[i][1]), fmaxf(s[i][2], s[i][3]));
#pragma unroll
            for (int w = 8; w >= 1; w >>= 1) mx = fmaxf(mx, __shfl_xor_sync(0xffffffffu, mx, w));
            float mnew = fmaxf(mi[i], mx);
            float rs = 0.f;
#pragma unroll
            for (int j = 0; j < 4; j++) {
                float p = __expf(s[i][j] - mnew);
                s[i][j] = p;
                rs += p;
            }
#pragma unroll
            for (int w = 8; w >= 1; w >>= 1) rs += __shfl_xor_sync(0xffffffffu, rs, w);
            float alpha = __expf(mi[i] - mnew);
            li[i] = li[i] * alpha + rs;
            mi[i] = mnew;
            unsigned long long ad = pk2(alpha, alpha);
#pragma unroll
            for (int jp = 0; jp < 4; jp++) op[i][jp] = mul2(op[i][jp], ad);
        }

        // write P transposed: Ps[n][m]
#pragma unroll
        for (int i = 0; i < 4; i++)
#pragma unroll
            for (int j = 0; j < 4; j++)
                Ps[(tn * 4 + j) * 132 + tm * 4 + i] = s[i][j];
        __syncthreads();

        // O += P V
#pragma unroll 4
        for (int n = 0; n < 64; n++) {
            float4 p = *(const float4*)&Ps[n * 132 + tm * 4];
            ulonglong2 v0 = *(const ulonglong2*)&Vs[n * 132 + tn * 8];
            ulonglong2 v1 = *(const ulonglong2*)&Vs[n * 132 + tn * 8 + 4];
            float pf[4] = {p.x, p.y, p.z, p.w};
#pragma unroll
            for (int i = 0; i < 4; i++) {
                unsigned long long p2 = pk2(pf[i], pf[i]);
                fma2(op[i][0], p2, v0.x);
                fma2(op[i][1], p2, v0.y);
                fma2(op[i][2], p2, v1.x);
                fma2(op[i][3], p2, v1.y);
            }
        }
        __syncthreads();
    }

#pragma unroll
    for (int i = 0; i < 4; i++) {
        float inv = 1.0f / li[i];
        float c[8];
        upk2(op[i][0], c[0], c[1]);
        upk2(op[i][1], c[2], c[3]);
        upk2(op[i][2], c[4], c[5]);
        upk2(op[i][3], c[6], c[7]);
        float* dst = out + (size_t)(m0 + tm * 4 + i) * DM + h * HD + tn * 8;
        *(float4*)dst       = make_float4(c[0] * inv, c[1] * inv, c[2] * inv, c[3] * inv);
        *(float4*)(dst + 4) = make_float4(c[4] * inv, c[5] * inv, c[6] * inv, c[7] * inv);
    }
}

// ---------------- launch ----------------------------------------------------
extern "C" void kernel_launch(void* const* d_in, const int* in_sizes, int n_in,
                              void* d_out, int out_size)
{
    const float* h = (const float*)d_in[0];
    const float *Wq, *Wk, *Wv, *bq, *bk, *bv, *dq, *uq, *dk, *uk, *dv, *uv;

    if (in_sizes[2] < 10000) {
        // reference-signature order: h, Wq, bq, Wk, bk, Wv, bv, qd, qu, kd, ku, vd, vu
        Wq = (const float*)d_in[1];  bq = (const float*)d_in[2];
        Wk = (const float*)d_in[3];  bk = (const float*)d_in[4];
        Wv = (const float*)d_in[5];  bv = (const float*)d_in[6];
        dq = (const float*)d_in[7];  uq = (const float*)d_in[8];
        dk = (const float*)d_in[9];  uk = (const float*)d_in[10];
        dv = (const float*)d_in[11]; uv = (const float*)d_in[12];
    } else {
        // setup_inputs dict order: h, Wq, Wk, Wv, bq, bk, bv, qd, kd, vd, qu, ku, vu
        Wq = (const float*)d_in[1];  Wk = (const float*)d_in[2];  Wv = (const float*)d_in[3];
        bq = (const float*)d_in[4];  bk = (const float*)d_in[5];  bv = (const float*)d_in[6];
        dq = (const float*)d_in[7];  dk = (const float*)d_in[8];  dv = (const float*)d_in[9];
        uq = (const float*)d_in[10]; uk = (const float*)d_in[11]; uv = (const float*)d_in[12];
    }
    const float* rmsq = (const float*)d_in[13];
    const float* rmsk = (const float*)d_in[14];
    const float* rc   = (const float*)d_in[15];
    const float* rs   = (const float*)d_in[16];
    float* out = (float*)d_out;

    cudaFuncSetAttribute(attn_kernel, cudaFuncAttributeMaxDynamicSharedMemorySize, ATT_SMEM_BYTES);

    qkv_gemm_kernel<<<dim3(24, 24, 3), 256>>>(h, Wq, Wk, Wv, bq, bk, bv);
    lora_down_kernel<<<dim3(32, 3), 256>>>(h, dq, dk, dv);
    lora_up_kernel<<<dim3(48, 16, 3), 256>>>(uq, uk, uv);
    rms_rope_kernel<<<dim3(3072, 24, 2), 128>>>(rmsq, rmsk, rc, rs);
    attn_kernel<<<dim3(24, NH), 512, ATT_SMEM_BYTES>>>(out);
}

// round 5
// speedup vs baseline: 1.2493x; 1.2493x over previous
#include <cuda_runtime.h>
#include <math.h>

#define SQ 3072
#define DM 3072
#define NH 24
#define HD 128
#define BLKROWS 2048

__device__ float g_q[SQ * DM];
__device__ float g_k[SQ * DM];
__device__ float g_v[SQ * DM];
__device__ float g_t[3 * 1024 * 64];

// ---- packed fp32x2 helpers ----
__device__ __forceinline__ unsigned long long pk2(float lo, float hi) {
    unsigned long long r;
    asm("mov.b64 %0, {%1, %2};" : "=l"(r) : "f"(lo), "f"(hi));
    return r;
}
__device__ __forceinline__ void upk2(unsigned long long v, float& lo, float& hi) {
    asm("mov.b64 {%0, %1}, %2;" : "=f"(lo), "=f"(hi) : "l"(v));
}
__device__ __forceinline__ void fma2(unsigned long long& d, unsigned long long a, unsigned long long b) {
    asm("fma.rn.f32x2 %0, %1, %2, %0;" : "+l"(d) : "l"(a), "l"(b));
}
__device__ __forceinline__ unsigned long long mul2(unsigned long long a, unsigned long long b) {
    unsigned long long r;
    asm("mul.rn.f32x2 %0, %1, %2;" : "=l"(r) : "l"(a), "l"(b));
    return r;
}

// ---- tf32 mma helpers ----
__device__ __forceinline__ unsigned f2tf(float x) {
    unsigned u;
    asm("cvt.rna.tf32.f32 %0, %1;" : "=r"(u) : "f"(x));
    return u;
}
__device__ __forceinline__ void split(float x, unsigned& hi, unsigned& lo) {
    hi = f2tf(x);
    lo = f2tf(x - __uint_as_float(hi));
}
__device__ __forceinline__ void mma8(float* c, const unsigned* a, const unsigned* b) {
    asm volatile(
        "mma.sync.aligned.m16n8k8.row.col.f32.tf32.tf32.f32 "
        "{%0,%1,%2,%3}, {%4,%5,%6,%7}, {%8,%9}, {%0,%1,%2,%3};\n"
        : "+f"(c[0]), "+f"(c[1]), "+f"(c[2]), "+f"(c[3])
        : "r"(a[0]), "r"(a[1]), "r"(a[2]), "r"(a[3]), "r"(b[0]), "r"(b[1]));
}
__device__ __forceinline__ void cpa(unsigned dst, const float* src) {
    asm volatile("cp.async.cg.shared.global [%0], [%1], 16;\n" :: "r"(dst), "l"(src));
}
__device__ __forceinline__ void cp_commit() { asm volatile("cp.async.commit_group;\n"); }
template <int N> __device__ __forceinline__ void cp_wait() {
    asm volatile("cp.async.wait_group %0;\n" :: "n"(N));
}

// ---- 1) QKV GEMM (3xTF32 tensor cores): C = h @ W.T + b ----
// 128x128 tile, BK=32, 8 warps (2x4, 64x32 warp tiles), cp.async double buffer.
// Logical-k permutation: mma k-slot lam <-> phys 2*lam, slot lam+4 <-> 2*lam+1,
// applied to BOTH A and B fragments -> contiguous float2 smem loads, no ldmatrix.
#define GS 40
#define GEMM_SMEM_BYTES (2 * 2 * 128 * GS * 4)

__global__ __launch_bounds__(256) void qkv_gemm_kernel(
    const float* __restrict__ A,
    const float* __restrict__ Wq, const float* __restrict__ Wk, const float* __restrict__ Wv,
    const float* __restrict__ bq, const float* __restrict__ bk, const float* __restrict__ bv)
{
    extern __shared__ float sm[];
    float* As = sm;                 // [2][128][GS]
    float* Bs = sm + 2 * 128 * GS;  // [2][128][GS]

    const int z = blockIdx.z;
    const float* __restrict__ W = (z == 0) ? Wq : (z == 1) ? Wk : Wv;
    const float* __restrict__ bias = (z == 0) ? bq : (z == 1) ? bk : bv;
    float* C = (z == 0) ? g_q : (z == 1) ? g_k : g_v;

    const int tid = threadIdx.x;
    const int m0 = blockIdx.y * 128;
    const int n0 = blockIdx.x * 128;
    const int lane = tid & 31;
    const int warp = tid >> 5;
    const int g = lane >> 2;
    const int lam = lane & 3;
    const int mw = warp >> 2;  // 0..1
    const int nw = warp & 3;   // 0..3

    unsigned sA = (unsigned)__cvta_generic_to_shared(As);
    unsigned sB = (unsigned)__cvta_generic_to_shared(Bs);

    float acc[4][4][4];
#pragma unroll
    for (int i = 0; i < 4; i++)
#pragma unroll
        for (int j = 0; j < 4; j++)
#pragma unroll
            for (int r = 0; r < 4; r++) acc[i][j][r] = 0.f;

    const int NT = DM / 32;  // 96

    auto issue_tile = [&](int t, int b) {
        int k0 = t * 32;
#pragma unroll
        for (int j = 0; j < 4; j++) {
            int cid = tid + 256 * j;
            int row = cid >> 3, c4 = (cid & 7) * 4;
            cpa(sA + (unsigned)(((b * 128 + row) * GS + c4) * 4),
                A + (size_t)(m0 + row) * DM + k0 + c4);
            cpa(sB + (unsigned)(((b * 128 + row) * GS + c4) * 4),
                W + (size_t)(n0 + row) * DM + k0 + c4);
        }
    };

    issue_tile(0, 0); cp_commit();
    issue_tile(1, 1); cp_commit();

    for (int it = 0; it < NT; it++) {
        cp_wait<1>();
        __syncthreads();
        const float* Ab = As + (it & 1) * 128 * GS;
        const float* Bb = Bs + (it & 1) * 128 * GS;

#pragma unroll
        for (int kt = 0; kt < 4; kt++) {
            unsigned Ah[4][4], Al[4][4], Bh[4][2], Bl[4][2];
#pragma unroll
            for (int i = 0; i < 4; i++) {
                int r0 = mw * 64 + 16 * i + g;
                float2 a01 = *(const float2*)(Ab + r0 * GS + kt * 8 + 2 * lam);
                float2 a23 = *(const float2*)(Ab + (r0 + 8) * GS + kt * 8 + 2 * lam);
                split(a01.x, Ah[i][0], Al[i][0]);
                split(a23.x, Ah[i][1], Al[i][1]);
                split(a01.y, Ah[i][2], Al[i][2]);
                split(a23.y, Ah[i][3], Al[i][3]);
            }
#pragma unroll
            for (int j = 0; j < 4; j++) {
                int n = nw * 32 + 8 * j + g;
                float2 b = *(const float2*)(Bb + n * GS + kt * 8 + 2 * lam);
                split(b.x, Bh[j][0], Bl[j][0]);
                split(b.y, Bh[j][1], Bl[j][1]);
            }
#pragma unroll
            for (int i = 0; i < 4; i++)
#pragma unroll
                for (int j = 0; j < 4; j++) {
                    mma8(acc[i][j], Ah[i], Bh[j]);
                    mma8(acc[i][j], Ah[i], Bl[j]);
                    mma8(acc[i][j], Al[i], Bh[j]);
                }
        }
        __syncthreads();
        if (it + 2 < NT) issue_tile(it + 2, it & 1);
        cp_commit();
    }

#pragma unroll
    for (int j = 0; j < 4; j++) {
        int c = n0 + nw * 32 + 8 * j + 2 * lam;
        float2 bj = *(const float2*)(bias + c);
#pragma unroll
        for (int i = 0; i < 4; i++) {
            int r0 = m0 + mw * 64 + 16 * i + g;
            *(float2*)(C + (size_t)r0 * DM + c) =
                make_float2(acc[i][j][0] + bj.x, acc[i][j][1] + bj.y);
            *(float2*)(C + (size_t)(r0 + 8) * DM + c) =
                make_float2(acc[i][j][2] + bj.x, acc[i][j][3] + bj.y);
        }
    }
}

// ---- 2) LoRA down: t[x] = h[2048:,:] @ down[x].T ----
__global__ __launch_bounds__(256) void lora_down_kernel(
    const float* __restrict__ h,
    const float* __restrict__ dq, const float* __restrict__ dk, const float* __restrict__ dv)
{
    const int x = blockIdx.y;
    const float* __restrict__ D = (x == 0) ? dq : (x == 1) ? dk : dv;
    const int i0 = blockIdx.x * 32;
    __shared__ float hs[32][65];
    __shared__ float ds[64][65];
    const int tid = threadIdx.x;
    const int r = tid & 31;
    const int c0 = (tid >> 5) * 8;
    float acc[8] = {0.f, 0.f, 0.f, 0.f, 0.f, 0.f, 0.f, 0.f};

    for (int k0 = 0; k0 < DM; k0 += 64) {
#pragma unroll
        for (int t = 0; t < 8; t++) {
            int idx = tid + t * 256;
            int rr = idx >> 6, cc = idx & 63;
            hs[rr][cc] = h[(size_t)(BLKROWS + i0 + rr) * DM + k0 + cc];
        }
#pragma unroll
        for (int t = 0; t < 16; t++) {
            int idx = tid + t * 256;
            int rr = idx >> 6, cc = idx & 63;
            ds[rr][cc] = D[(size_t)rr * DM + k0 + cc];
        }
        __syncthreads();
#pragma unroll 8
        for (int kk = 0; kk < 64; kk++) {
            float a = hs[r][kk];
#pragma unroll
            for (int j = 0; j < 8; j++) acc[j] += a * ds[c0 + j][kk];
        }
        __syncthreads();
    }
#pragma unroll
    for (int j = 0; j < 8; j++)
        g_t[x * 65536 + (i0 + r) * 64 + c0 + j] = acc[j];
}

// ---- 3) LoRA up: C[2048+i, n] += t @ up.T ----
__global__ __launch_bounds__(256) void lora_up_kernel(
    const float* __restrict__ uq, const float* __restrict__ uk, const float* __restrict__ uv)
{
    const int x = blockIdx.z;
    const float* __restrict__ U = (x == 0) ? uq : (x == 1) ? uk : uv;
    float* C = (x == 0) ? g_q : (x == 1) ? g_k : g_v;
    const int n0 = blockIdx.x * 64;
    const int i0 = blockIdx.y * 64;
    __shared__ float ts[64][68];
    __shared__ float us[64][68];
    const int tid = threadIdx.x;
#pragma unroll
    for (int t = 0; t < 16; t++) {
        int idx = tid + t * 256;
        int ii = idx >> 6, rr = idx & 63;
        ts[rr][ii] = g_t[x * 65536 + (i0 + ii) * 64 + rr];
        us[rr][ii] = U[(size_t)(n0 + ii) * 64 + rr];
    }
    __syncthreads();
    const int tm = tid >> 4, tn = tid & 15;
    unsigned long long acc[4][2];
#pragma unroll
    for (int i = 0; i < 4; i++) { acc[i][0] = 0ull; acc[i][1] = 0ull; }
#pragma unroll 8
    for (int rr = 0; rr < 64; rr++) {
        float4 a = *(const float4*)&ts[rr][tm * 4];
        ulonglong2 b = *(const ulonglong2*)&us[rr][tn * 4];
        float af[4] = {a.x, a.y, a.z, a.w};
#pragma unroll
        for (int i = 0; i < 4; i++) {
            unsigned long long a2 = pk2(af[i], af[i]);
            fma2(acc[i][0], a2, b.x);
            fma2(acc[i][1], a2, b.y);
        }
    }
#pragma unroll
    for (int i = 0; i < 4; i++) {
        float c0, c1, c2, c3;
        upk2(acc[i][0], c0, c1);
        upk2(acc[i][1], c2, c3);
        float* dst = C + (size_t)(BLKROWS + i0 + tm * 4 + i) * DM + n0 + tn * 4;
        float4 old = *(float4*)dst;
        old.x += c0; old.y += c1; old.z += c2; old.w += c3;
        *(float4*)dst = old;
    }
}

// ---- 4) RMSNorm + RoPE in place on q/k ----
__global__ __launch_bounds__(128) void rms_rope_kernel(
    const float* __restrict__ wq, const float* __restrict__ wk,
    const float* __restrict__ cosb, const float* __restrict__ sinb)
{
    const int s = blockIdx.x;
    const int hh = blockIdx.y;
    const int qk = blockIdx.z;
    const int d = threadIdx.x;
    float* buf = qk ? g_k : g_q;
    const float* w = qk ? wk : wq;
    size_t idx = (size_t)s * DM + hh * HD + d;
    float x = buf[idx];
    float v = x * x;
#pragma unroll
    for (int o = 16; o; o >>= 1) v += __shfl_xor_sync(0xffffffffu, v, o);
    __shared__ float red[4];
    if ((d & 31) == 0) red[d >> 5] = v;
    __syncthreads();
    float tot = red[0] + red[1] + red[2] + red[3];
    float y = x * rsqrtf(tot * (1.0f / 128.0f) + 1e-6f) * w[d];
    float partner = __shfl_xor_sync(0xffffffffu, y, 1);
    float xr = (d & 1) ? partner : -partner;
    buf[idx] = y * cosb[s * HD + d] + xr * sinb[s * HD + d];
}

// ---- 5) Flash attention (fp32, f32x2 FMAs) ----
// image rows (<2048) attend all 3072 cols; cond rows attend [2048,3072).
#define ATT_SMEM_FLOATS (128 * 132 + 128 * 68 + 64 * 132 + 64 * 132)
#define ATT_SMEM_BYTES (ATT_SMEM_FLOATS * 4)

__global__ __launch_bounds__(512) void attn_kernel(float* __restrict__ out)
{
    extern __shared__ float sm[];
    float* Qs = sm;
    float* Ks = Qs + 128 * 132;
    float* Vs = Ks + 128 * 68;
    float* Ps = Vs + 64 * 132;

    const int m0 = blockIdx.x * 128;
    const int h = blockIdx.y;
    const int tid = threadIdx.x;
    const int tm = tid >> 4;
    const int tn = tid & 15;
    const float sc = 0.08838834764831845f;

    for (int idx = tid; idx < 128 * 128; idx += 512) {
        int m = idx >> 7, d = idx & 127;
        Qs[d * 132 + m] = g_q[(size_t)(m0 + m) * DM + h * HD + d] * sc;
    }

    unsigned long long op[4][4];
#pragma unroll
    for (int i = 0; i < 4; i++)
#pragma unroll
        for (int j = 0; j < 4; j++) op[i][j] = 0ull;
    float mi[4] = {-1e30f, -1e30f, -1e30f, -1e30f};
    float li[4] = {0.f, 0.f, 0.f, 0.f};
    const int n_start = (m0 >= BLKROWS) ? BLKROWS : 0;

    for (int n0 = n_start; n0 < SQ; n0 += 64) {
        for (int idx = tid; idx < 64 * 128; idx += 512) {
            int n = idx >> 7, d = idx & 127;
            size_t gg = (size_t)(n0 + n) * DM + h * HD + d;
            Ks[d * 68 + n] = g_k[gg];
            Vs[n * 132 + d] = g_v[gg];
        }
        __syncthreads();

        unsigned long long sp[4][2];
#pragma unroll
        for (int i = 0; i < 4; i++) { sp[i][0] = 0ull; sp[i][1] = 0ull; }
#pragma unroll 8
        for (int d = 0; d < 128; d++) {
            float4 a = *(const float4*)&Qs[d * 132 + tm * 4];
            ulonglong2 b = *(const ulonglong2*)&Ks[d * 68 + tn * 4];
            float af[4] = {a.x, a.y, a.z, a.w};
#pragma unroll
            for (int i = 0; i < 4; i++) {
                unsigned long long a2 = pk2(af[i], af[i]);
                fma2(sp[i][0], a2, b.x);
                fma2(sp[i][1], a2, b.y);
            }
        }
        float s[4][4];
#pragma unroll
        for (int i = 0; i < 4; i++) {
            upk2(sp[i][0], s[i][0], s[i][1]);
            upk2(sp[i][1], s[i][2], s[i][3]);
        }
#pragma unroll
        for (int i = 0; i < 4; i++) {
            float mx = fmaxf(fmaxf(s[i][0], s[i][1]), fmaxf(s[i][2], s[i][3]));
#pragma unroll
            for (int w = 8; w >= 1; w >>= 1) mx = fmaxf(mx, __shfl_xor_sync(0xffffffffu, mx, w));
            float mnew = fmaxf(mi[i], mx);
            float rs = 0.f;
#pragma unroll
            for (int j = 0; j < 4; j++) {
                float p = __expf(s[i][j] - mnew);
                s[i][j] = p;
                rs += p;
            }
#pragma unroll
            for (int w = 8; w >= 1; w >>= 1) rs += __shfl_xor_sync(0xffffffffu, rs, w);
            float alpha = __expf(mi[i] - mnew);
            li[i] = li[i] * alpha + rs;
            mi[i] = mnew;
            unsigned long long ad = pk2(alpha, alpha);
#pragma unroll
            for (int jp = 0; jp < 4; jp++) op[i][jp] = mul2(op[i][jp], ad);
        }
#pragma unroll
        for (int i = 0; i < 4; i++)
#pragma unroll
            for (int j = 0; j < 4; j++)
                Ps[(tn * 4 + j) * 132 + tm * 4 + i] = s[i][j];
        __syncthreads();

#pragma unroll 4
        for (int n = 0; n < 64; n++) {
            float4 p = *(const float4*)&Ps[n * 132 + tm * 4];
            ulonglong2 v0 = *(const ulonglong2*)&Vs[n * 132 + tn * 8];
            ulonglong2 v1 = *(const ulonglong2*)&Vs[n * 132 + tn * 8 + 4];
            float pf[4] = {p.x, p.y, p.z, p.w};
#pragma unroll
            for (int i = 0; i < 4; i++) {
                unsigned long long p2 = pk2(pf[i], pf[i]);
                fma2(op[i][0], p2, v0.x);
                fma2(op[i][1], p2, v0.y);
                fma2(op[i][2], p2, v1.x);
                fma2(op[i][3], p2, v1.y);
            }
        }
        __syncthreads();
    }

#pragma unroll
    for (int i = 0; i < 4; i++) {
        float inv = 1.0f / li[i];
        float c[8];
        upk2(op[i][0], c[0], c[1]);
        upk2(op[i][1], c[2], c[3]);
        upk2(op[i][2], c[4], c[5]);
        upk2(op[i][3], c[6], c[7]);
        float* dst = out + (size_t)(m0 + tm * 4 + i) * DM + h * HD + tn * 8;
        *(float4*)dst = make_float4(c[0] * inv, c[1] * inv, c[2] * inv, c[3] * inv);
        *(float4*)(dst + 4) = make_float4(c[4] * inv, c[5] * inv, c[6] * inv, c[7] * inv);
    }
}

// ---- launch ----
extern "C" void kernel_launch(void* const* d_in, const int* in_sizes, int n_in,
                              void* d_out, int out_size)
{
    const float* h = (const float*)d_in[0];
    const float *Wq, *Wk, *Wv, *bq, *bk, *bv, *dq, *uq, *dk, *uk, *dv, *uv;

    if (in_sizes[2] < 10000) {
        Wq = (const float*)d_in[1];  bq = (const float*)d_in[2];
        Wk = (const float*)d_in[3];  bk = (const float*)d_in[4];
        Wv = (const float*)d_in[5];  bv = (const float*)d_in[6];
        dq = (const float*)d_in[7];  uq = (const float*)d_in[8];
        dk = (const float*)d_in[9];  uk = (const float*)d_in[10];
        dv = (const float*)d_in[11]; uv = (const float*)d_in[12];
    } else {
        Wq = (const float*)d_in[1];  Wk = (const float*)d_in[2];  Wv = (const float*)d_in[3];
        bq = (const float*)d_in[4];  bk = (const float*)d_in[5];  bv = (const float*)d_in[6];
        dq = (const float*)d_in[7];  dk = (const float*)d_in[8];  dv = (const float*)d_in[9];
        uq = (const float*)d_in[10]; uk = (const float*)d_in[11]; uv = (const float*)d_in[12];
    }
    const float* rmsq = (const float*)d_in[13];
    const float* rmsk = (const float*)d_in[14];
    const float* rc   = (const float*)d_in[15];
    const float* rs   = (const float*)d_in[16];
    float* out = (float*)d_out;

    cudaFuncSetAttribute(qkv_gemm_kernel, cudaFuncAttributeMaxDynamicSharedMemorySize, GEMM_SMEM_BYTES);
    cudaFuncSetAttribute(attn_kernel, cudaFuncAttributeMaxDynamicSharedMemorySize, ATT_SMEM_BYTES);

    qkv_gemm_kernel<<<dim3(24, 24, 3), 256, GEMM_SMEM_BYTES>>>(h, Wq, Wk, Wv, bq, bk, bv);
    lora_down_kernel<<<dim3(32, 3), 256>>>(h, dq, dk, dv);
    lora_up_kernel<<<dim3(48, 16, 3), 256>>>(uq, uk, uv);
    rms_rope_kernel<<<dim3(3072, 24, 2), 128>>>(rmsq, rmsk, rc, rs);
    attn_kernel<<<dim3(24, NH), 512, ATT_SMEM_BYTES>>>(out);
}

// round 6
// speedup vs baseline: 2.4763x; 1.9821x over previous
#include <cuda_runtime.h>
#include <math.h>

#define SQ 3072
#define DM 3072
#define NH 24
#define HD 128
#define BLKROWS 2048
#define HWORDS (SQ * DM / 2)

__device__ float g_q[SQ * DM];
__device__ float g_k[SQ * DM];
__device__ float g_v[SQ * DM];
__device__ float g_t[3 * 1024 * 64];
__device__ unsigned g_hh[HWORDS], g_hl[HWORDS];
__device__ unsigned g_wh[3][HWORDS], g_wl[3][HWORDS];
__device__ unsigned g_qh[HWORDS], g_ql[HWORDS], g_kh[HWORDS], g_kl[HWORDS];
__device__ unsigned g_vth[HWORDS], g_vtl[HWORDS];

// ---- helpers ----
__device__ __forceinline__ unsigned long long pk2(float lo, float hi) {
    unsigned long long r;
    asm("mov.b64 %0, {%1, %2};" : "=l"(r) : "f"(lo), "f"(hi));
    return r;
}
__device__ __forceinline__ void upk2(unsigned long long v, float& lo, float& hi) {
    asm("mov.b64 {%0, %1}, %2;" : "=f"(lo), "=f"(hi) : "l"(v));
}
__device__ __forceinline__ void fma2(unsigned long long& d, unsigned long long a, unsigned long long b) {
    asm("fma.rn.f32x2 %0, %1, %2, %0;" : "+l"(d) : "l"(a), "l"(b));
}
// pack (x0 -> low16, x1 -> high16) as bf16x2
__device__ __forceinline__ unsigned bfp(float x0, float x1) {
    unsigned r;
    asm("cvt.rn.bf16x2.f32 %0, %1, %2;" : "=r"(r) : "f"(x1), "f"(x0));
    return r;
}
__device__ __forceinline__ float bflo(unsigned u) { return __uint_as_float(u << 16); }
__device__ __forceinline__ float bfhi(unsigned u) { return __uint_as_float(u & 0xffff0000u); }
__device__ __forceinline__ unsigned bfres(float x0, float x1, unsigned hi) {
    return bfp(x0 - bflo(hi), x1 - bfhi(hi));
}
__device__ __forceinline__ void mmabf(float* c, const unsigned* a, const unsigned* b) {
    asm volatile(
        "mma.sync.aligned.m16n8k16.row.col.f32.bf16.bf16.f32 "
        "{%0,%1,%2,%3}, {%4,%5,%6,%7}, {%8,%9}, {%0,%1,%2,%3};\n"
        : "+f"(c[0]), "+f"(c[1]), "+f"(c[2]), "+f"(c[3])
        : "r"(a[0]), "r"(a[1]), "r"(a[2]), "r"(a[3]), "r"(b[0]), "r"(b[1]));
}
__device__ __forceinline__ void cpa(unsigned dst, const void* src) {
    asm volatile("cp.async.cg.shared.global [%0], [%1], 16;\n" :: "r"(dst), "l"(src));
}
__device__ __forceinline__ void cp_commit() { asm volatile("cp.async.commit_group;\n"); }
template <int N> __device__ __forceinline__ void cp_wait() {
    asm volatile("cp.async.wait_group %0;\n" :: "n"(N));
}

// ---- 0) split h + W into bf16 hi/lo with k16-group permutation ----
// phys word p in 8-word group holds logical word l = (p&1) ? p/2+4 : p/2
__global__ __launch_bounds__(256) void split_hw_kernel(
    const float* __restrict__ h, const float* __restrict__ Wq,
    const float* __restrict__ Wk, const float* __restrict__ Wv)
{
    const int a = blockIdx.y;
    const float* src = (a == 0) ? h : (a == 1) ? Wq : (a == 2) ? Wk : Wv;
    unsigned* dh = (a == 0) ? g_hh : g_wh[a - 1];
    unsigned* dl = (a == 0) ? g_hl : g_wl[a - 1];
    int wi = blockIdx.x * 256 + threadIdx.x;
    int p = wi & 7;
    int l = (p & 1) ? (p >> 1) + 4 : (p >> 1);
    float2 v = *(const float2*)(src + (size_t)(wi & ~7) * 2 + 2 * l);
    unsigned hi = bfp(v.x, v.y);
    dh[wi] = hi;
    dl[wi] = bfres(v.x, v.y, hi);
}

// ---- 1) QKV GEMM (bf16 3-term tensor cores): C = h @ W.T + b ----
// 128x128 tile, BK=32, 8 warps (2x4), warp tile 64x32, cp.async double buffer.
#define GRS 40  // smem row stride in bf16 elems
#define GARR (128 * GRS)
#define GEMM_SMEM_BYTES (8 * GARR * 2)  // 4 arrays x 2 buffers x 128x40 bf16

__global__ __launch_bounds__(256) void qkv_gemm_kernel(
    const float* __restrict__ bq, const float* __restrict__ bk, const float* __restrict__ bv)
{
    extern __shared__ unsigned short us[];
    // layout (u16 units): [buf][Ah, Al, Bh, Bl] each GARR
    const int z = blockIdx.z;
    const unsigned* Ah = g_hh;
    const unsigned* Al = g_hl;
    const unsigned* Bh = g_wh[z];
    const unsigned* Bl = g_wl[z];
    const float* bias = (z == 0) ? bq : (z == 1) ? bk : bv;
    float* C = (z == 0) ? g_q : (z == 1) ? g_k : g_v;

    const int tid = threadIdx.x;
    const int m0 = blockIdx.y * 128;
    const int n0 = blockIdx.x * 128;
    const int lane = tid & 31;
    const int warp = tid >> 5;
    const int g = lane >> 2;
    const int lam = lane & 3;
    const int mw = warp >> 2;
    const int nw = warp & 3;

    unsigned sbase = (unsigned)__cvta_generic_to_shared(us);

    float acc[4][4][4];
#pragma unroll
    for (int i = 0; i < 4; i++)
#pragma unroll
        for (int j = 0; j < 4; j++)
#pragma unroll
            for (int r = 0; r < 4; r++) acc[i][j][r] = 0.f;

    const int NT = DM / 32;  // 96

    auto issue_tile = [&](int t, int b) {
        // per array: 512 chunks of 16B; rows 128, 4 chunks/row
        int kw = t * 16;  // word offset in k
        unsigned dst0 = sbase + (unsigned)(b * 4 * GARR * 2);
#pragma unroll
        for (int j = 0; j < 8; j++) {
            int cid = tid + 256 * j;
            int arr = cid >> 9;          // 0..3: Ah, Al, Bh, Bl
            int c2 = cid & 511;
            int row = c2 >> 2, c = c2 & 3;
            const unsigned* srcb = (arr == 0) ? Ah : (arr == 1) ? Al : (arr == 2) ? Bh : Bl;
            int grow = ((arr < 2) ? m0 : n0) + row;
            cpa(dst0 + (unsigned)((arr * GARR + row * GRS) * 2 + c * 16),
                srcb + (size_t)grow * (DM / 2) + kw + c * 4);
        }
    };

    issue_tile(0, 0); cp_commit();
    issue_tile(1, 1); cp_commit();

    for (int it = 0; it < NT; it++) {
        cp_wait<1>();
        __syncthreads();
        const unsigned short* bb = us + (it & 1) * 4 * GARR;

#pragma unroll
        for (int kt = 0; kt < 2; kt++) {
            unsigned Af[2][4][4], Bf[2][4][2];
#pragma unroll
            for (int i = 0; i < 4; i++) {
                int r0 = mw * 64 + 16 * i + g;
#pragma unroll
                for (int hl = 0; hl < 2; hl++) {
                    const unsigned short* ap = bb + hl * GARR;
                    unsigned long long v0 = *(const unsigned long long*)(ap + r0 * GRS + kt * 16 + lam * 4);
                    unsigned long long v1 = *(const unsigned long long*)(ap + (r0 + 8) * GRS + kt * 16 + lam * 4);
                    Af[hl][i][0] = (unsigned)v0; Af[hl][i][2] = (unsigned)(v0 >> 32);
                    Af[hl][i][1] = (unsigned)v1; Af[hl][i][3] = (unsigned)(v1 >> 32);
                }
            }
#pragma unroll
            for (int j = 0; j < 4; j++) {
                int n = nw * 32 + 8 * j + g;
#pragma unroll
                for (int hl = 0; hl < 2; hl++) {
                    const unsigned short* bp = bb + (2 + hl) * GARR;
                    unsigned long long v = *(const unsigned long long*)(bp + n * GRS + kt * 16 + lam * 4);
                    Bf[hl][j][0] = (unsigned)v; Bf[hl][j][1] = (unsigned)(v >> 32);
                }
            }
#pragma unroll
            for (int i = 0; i < 4; i++)
#pragma unroll
                for (int j = 0; j < 4; j++) {
                    mmabf(acc[i][j], Af[0][i], Bf[0][j]);
                    mmabf(acc[i][j], Af[0][i], Bf[1][j]);
                    mmabf(acc[i][j], Af[1][i], Bf[0][j]);
                }
        }
        __syncthreads();
        if (it + 2 < NT) issue_tile(it + 2, it & 1);
        cp_commit();
    }

#pragma unroll
    for (int j = 0; j < 4; j++) {
        int c = n0 + nw * 32 + 8 * j + 2 * lam;
        float2 bj = *(const float2*)(bias + c);
#pragma unroll
        for (int i = 0; i < 4; i++) {
            int r0 = m0 + mw * 64 + 16 * i + g;
            *(float2*)(C + (size_t)r0 * DM + c) =
                make_float2(acc[i][j][0] + bj.x, acc[i][j][1] + bj.y);
            *(float2*)(C + (size_t)(r0 + 8) * DM + c) =
                make_float2(acc[i][j][2] + bj.x, acc[i][j][3] + bj.y);
        }
    }
}

// ---- 2) LoRA down ----
__global__ __launch_bounds__(256) void lora_down_kernel(
    const float* __restrict__ h,
    const float* __restrict__ dq, const float* __restrict__ dk, const float* __restrict__ dv)
{
    const int x = blockIdx.y;
    const float* __restrict__ D = (x == 0) ? dq : (x == 1) ? dk : dv;
    const int i0 = blockIdx.x * 32;
    __shared__ float hs[32][65];
    __shared__ float ds[64][65];
    const int tid = threadIdx.x;
    const int r = tid & 31;
    const int c0 = (tid >> 5) * 8;
    float acc[8] = {0.f, 0.f, 0.f, 0.f, 0.f, 0.f, 0.f, 0.f};

    for (int k0 = 0; k0 < DM; k0 += 64) {
#pragma unroll
        for (int t = 0; t < 8; t++) {
            int idx = tid + t * 256;
            hs[idx >> 6][idx & 63] = h[(size_t)(BLKROWS + i0 + (idx >> 6)) * DM + k0 + (idx & 63)];
        }
#pragma unroll
        for (int t = 0; t < 16; t++) {
            int idx = tid + t * 256;
            ds[idx >> 6][idx & 63] = D[(size_t)(idx >> 6) * DM + k0 + (idx & 63)];
        }
        __syncthreads();
#pragma unroll 8
        for (int kk = 0; kk < 64; kk++) {
            float a = hs[r][kk];
#pragma unroll
            for (int j = 0; j < 8; j++) acc[j] += a * ds[c0 + j][kk];
        }
        __syncthreads();
    }
#pragma unroll
    for (int j = 0; j < 8; j++)
        g_t[x * 65536 + (i0 + r) * 64 + c0 + j] = acc[j];
}

// ---- 3) LoRA up ----
__global__ __launch_bounds__(256) void lora_up_kernel(
    const float* __restrict__ uq, const float* __restrict__ uk, const float* __restrict__ uv)
{
    const int x = blockIdx.z;
    const float* __restrict__ U = (x == 0) ? uq : (x == 1) ? uk : uv;
    float* C = (x == 0) ? g_q : (x == 1) ? g_k : g_v;
    const int n0 = blockIdx.x * 64;
    const int i0 = blockIdx.y * 64;
    __shared__ float ts[64][68];
    __shared__ float uss[64][68];
    const int tid = threadIdx.x;
#pragma unroll
    for (int t = 0; t < 16; t++) {
        int idx = tid + t * 256;
        int ii = idx >> 6, rr = idx & 63;
        ts[rr][ii] = g_t[x * 65536 + (i0 + ii) * 64 + rr];
        uss[rr][ii] = U[(size_t)(n0 + ii) * 64 + rr];
    }
    __syncthreads();
    const int tm = tid >> 4, tn = tid & 15;
    unsigned long long acc[4][2];
#pragma unroll
    for (int i = 0; i < 4; i++) { acc[i][0] = 0ull; acc[i][1] = 0ull; }
#pragma unroll 8
    for (int rr = 0; rr < 64; rr++) {
        float4 a = *(const float4*)&ts[rr][tm * 4];
        ulonglong2 b = *(const ulonglong2*)&uss[rr][tn * 4];
        float af[4] = {a.x, a.y, a.z, a.w};
#pragma unroll
        for (int i = 0; i < 4; i++) {
            unsigned long long a2 = pk2(af[i], af[i]);
            fma2(acc[i][0], a2, b.x);
            fma2(acc[i][1], a2, b.y);
        }
    }
#pragma unroll
    for (int i = 0; i < 4; i++) {
        float c0, c1, c2, c3;
        upk2(acc[i][0], c0, c1);
        upk2(acc[i][1], c2, c3);
        float* dst = C + (size_t)(BLKROWS + i0 + tm * 4 + i) * DM + n0 + tn * 4;
        float4 old = *(float4*)dst;
        old.x += c0; old.y += c1; old.z += c2; old.w += c3;
        *(float4*)dst = old;
    }
}

// ---- 4) RMSNorm + RoPE -> bf16 hi/lo split (d-permuted); Q pre-scaled ----
__global__ __launch_bounds__(128) void rms_rope_kernel(
    const float* __restrict__ wq, const float* __restrict__ wk,
    const float* __restrict__ cosb, const float* __restrict__ sinb)
{
    const int s = blockIdx.x;
    const int hh = blockIdx.y;
    const int qk = blockIdx.z;
    const int d = threadIdx.x;
    const float* buf = qk ? g_k : g_q;
    const float* w = qk ? wk : wq;
    unsigned* oh = qk ? g_kh : g_qh;
    unsigned* ol = qk ? g_kl : g_ql;

    size_t idx = (size_t)s * DM + hh * HD + d;
    float x = buf[idx];
    float v = x * x;
#pragma unroll
    for (int o = 16; o; o >>= 1) v += __shfl_xor_sync(0xffffffffu, v, o);
    __shared__ float red[4];
    if ((d & 31) == 0) red[d >> 5] = v;
    __syncthreads();
    float tot = red[0] + red[1] + red[2] + red[3];
    float y = x * rsqrtf(tot * (1.0f / 128.0f) + 1e-6f) * w[d];
    float partner = __shfl_xor_sync(0xffffffffu, y, 1);
    float xr = (d & 1) ? partner : -partner;
    float f = y * cosb[s * HD + d] + xr * sinb[s * HD + d];
    if (!qk) f *= 0.08838834764831845f;  // fold 1/sqrt(HD) into Q

    float mate = __shfl_xor_sync(0xffffffffu, f, 1);
    if (!(d & 1)) {
        int l = (d & 15) >> 1;
        int p = (l < 4) ? 2 * l : 2 * (l - 4) + 1;
        size_t wo = ((size_t)s * DM + hh * HD) / 2 + (d >> 4) * 8 + p;
        unsigned hi = bfp(f, mate);
        oh[wo] = hi;
        ol[wo] = bfres(f, mate, hi);
    }
}

// ---- 4b) V split + transpose: Vt[head][d][n], n k16-permuted ----
__global__ __launch_bounds__(256) void v_split_kernel()
{
    __shared__ float vs[64][129];
    const int s0 = blockIdx.x * 64;
    const int hh = blockIdx.y;
    const int tid = threadIdx.x;
    for (int t = tid; t < 64 * 128; t += 256) {
        int r = t >> 7, d = t & 127;
        vs[r][d] = g_v[(size_t)(s0 + r) * DM + hh * HD + d];
    }
    __syncthreads();
    for (int t = tid; t < 128 * 32; t += 256) {
        int d = t >> 5, wloc = t & 31;
        int p = wloc & 7;
        int l = (p & 1) ? (p >> 1) + 4 : (p >> 1);
        int n = (wloc & ~7) * 2 + 2 * l;
        float x0 = vs[n][d], x1 = vs[n + 1][d];
        unsigned hi = bfp(x0, x1);
        size_t o = ((size_t)hh * HD + d) * (SQ / 2) + s0 / 2 + wloc;
        g_vth[o] = hi;
        g_vtl[o] = bfres(x0, x1, hi);
    }
}

// ---- 5) Flash attention (bf16 3-term mma) ----
// block = 256 thr (8 warps), each warp owns 16 q rows; KV tiles of 64.
// image rows (<2048) attend all 3072 cols; cond rows attend [2048,3072).
#define KST 136                         // K smem row stride (u16)
#define VST 72                          // V smem row stride (u16)
#define ATT_SMEM_U16 (2 * (64 * KST + 128 * VST) * 2)  // hi+lo, 2 buffers
#define ATT_SMEM_BYTES (ATT_SMEM_U16 * 2)

__global__ __launch_bounds__(256) void attn_kernel(float* __restrict__ out)
{
    extern __shared__ unsigned short as[];
    // layout per buffer: Kh[64*KST], Kl[64*KST], Vh[128*VST], Vl[128*VST]
    const int BUFU = 2 * 64 * KST + 2 * 128 * VST;
    const int m0 = blockIdx.x * 128;
    const int h = blockIdx.y;
    const int tid = threadIdx.x;
    const int lane = tid & 31;
    const int warp = tid >> 5;
    const int g = lane >> 2;
    const int lam = lane & 3;
    const int qr = m0 + warp * 16;
    unsigned sbase = (unsigned)__cvta_generic_to_shared(as);

    // Q fragments in registers for whole KV loop
    unsigned qfh[8][4], qfl[8][4];
    {
        size_t b0 = ((size_t)(qr + g) * DM + h * HD) / 2;
        size_t b1 = ((size_t)(qr + g + 8) * DM + h * HD) / 2;
#pragma unroll
        for (int kt = 0; kt < 8; kt++) {
            unsigned long long h0 = *(const unsigned long long*)(g_qh + b0 + kt * 8 + 2 * lam);
            unsigned long long h1 = *(const unsigned long long*)(g_qh + b1 + kt * 8 + 2 * lam);
            unsigned long long l0 = *(const unsigned long long*)(g_ql + b0 + kt * 8 + 2 * lam);
            unsigned long long l1 = *(const unsigned long long*)(g_ql + b1 + kt * 8 + 2 * lam);
            qfh[kt][0] = (unsigned)h0; qfh[kt][2] = (unsigned)(h0 >> 32);
            qfh[kt][1] = (unsigned)h1; qfh[kt][3] = (unsigned)(h1 >> 32);
            qfl[kt][0] = (unsigned)l0; qfl[kt][2] = (unsigned)(l0 >> 32);
            qfl[kt][1] = (unsigned)l1; qfl[kt][3] = (unsigned)(l1 >> 32);
        }
    }

    float oa[16][4];
#pragma unroll
    for (int j = 0; j < 16; j++)
#pragma unroll
        for (int r = 0; r < 4; r++) oa[j][r] = 0.f;
    float mi0 = -1e30f, mi1 = -1e30f, li0 = 0.f, li1 = 0.f;

    const int n_start = (m0 >= BLKROWS) ? BLKROWS : 0;
    const int NTK = (SQ - n_start) / 64;

    auto issue = [&](int ti, int b) {
        int n0 = n_start + ti * 64;
        unsigned d0 = sbase + (unsigned)(b * BUFU * 2);
        // K: hi+lo, 64 rows x 16 chunks each
#pragma unroll
        for (int j = 0; j < 8; j++) {
            int cid = tid + 256 * j;
            int hl = cid >> 10, c2 = cid & 1023;
            int row = c2 >> 4, c = c2 & 15;
            const unsigned* src = (hl ? g_kl : g_kh) + ((size_t)(n0 + row) * DM + h * HD) / 2 + c * 4;
            cpa(d0 + (unsigned)((hl * 64 * KST + row * KST) * 2 + c * 16), src);
        }
        unsigned dv = d0 + (unsigned)(2 * 64 * KST * 2);
        // V: hi+lo, 128 rows x 8 chunks each
#pragma unroll
        for (int j = 0; j < 8; j++) {
            int cid = tid + 256 * j;
            int hl = cid >> 10, c2 = cid & 1023;
            int row = c2 >> 3, c = c2 & 7;
            const unsigned* src = (hl ? g_vtl : g_vth) + ((size_t)h * HD + row) * (SQ / 2) + n0 / 2 + c * 4;
            cpa(dv + (unsigned)((hl * 128 * VST + row * VST) * 2 + c * 16), src);
        }
    };

    issue(0, 0); cp_commit();

    for (int ti = 0; ti < NTK; ti++) {
        if (ti + 1 < NTK) { issue(ti + 1, (ti + 1) & 1); cp_commit(); cp_wait<1>(); }
        else cp_wait<0>();
        __syncthreads();
        const unsigned short* bb = as + (ti & 1) * BUFU;
        const unsigned short* Kh = bb;
        const unsigned short* Kl = bb + 64 * KST;
        const unsigned short* Vh = bb + 2 * 64 * KST;
        const unsigned short* Vl = Vh + 128 * VST;

        // S = Q K^T
        float s[8][4];
#pragma unroll
        for (int j = 0; j < 8; j++)
#pragma unroll
            for (int r = 0; r < 4; r++) s[j][r] = 0.f;
#pragma unroll
        for (int kt = 0; kt < 8; kt++) {
#pragma unroll
            for (int j = 0; j < 8; j++) {
                int row = 8 * j + g;
                unsigned long long vh = *(const unsigned long long*)(Kh + row * KST + kt * 16 + lam * 4);
                unsigned long long vl = *(const unsigned long long*)(Kl + row * KST + kt * 16 + lam * 4);
                unsigned bh[2] = {(unsigned)vh, (unsigned)(vh >> 32)};
                unsigned bl[2] = {(unsigned)vl, (unsigned)(vl >> 32)};
                mmabf(s[j], qfh[kt], bh);
                mmabf(s[j], qfh[kt], bl);
                mmabf(s[j], qfl[kt], bh);
            }
        }

        // online softmax; lane holds rows g (s[.][0..1]) and g+8 (s[.][2..3])
        float mx0 = -1e30f, mx1 = -1e30f;
#pragma unroll
        for (int j = 0; j < 8; j++) {
            mx0 = fmaxf(mx0, fmaxf(s[j][0], s[j][1]));
            mx1 = fmaxf(mx1, fmaxf(s[j][2], s[j][3]));
        }
        mx0 = fmaxf(mx0, __shfl_xor_sync(0xffffffffu, mx0, 1));
        mx0 = fmaxf(mx0, __shfl_xor_sync(0xffffffffu, mx0, 2));
        mx1 = fmaxf(mx1, __shfl_xor_sync(0xffffffffu, mx1, 1));
        mx1 = fmaxf(mx1, __shfl_xor_sync(0xffffffffu, mx1, 2));
        float mn0 = fmaxf(mi0, mx0), mn1 = fmaxf(mi1, mx1);
        float rs0 = 0.f, rs1 = 0.f;
#pragma unroll
        for (int j = 0; j < 8; j++) {
            s[j][0] = __expf(s[j][0] - mn0); rs0 += s[j][0];
            s[j][1] = __expf(s[j][1] - mn0); rs0 += s[j][1];
            s[j][2] = __expf(s[j][2] - mn1); rs1 += s[j][2];
            s[j][3] = __expf(s[j][3] - mn1); rs1 += s[j][3];
        }
        rs0 += __shfl_xor_sync(0xffffffffu, rs0, 1);
        rs0 += __shfl_xor_sync(0xffffffffu, rs0, 2);
        rs1 += __shfl_xor_sync(0xffffffffu, rs1, 1);
        rs1 += __shfl_xor_sync(0xffffffffu, rs1, 2);
        float al0 = __expf(mi0 - mn0), al1 = __expf(mi1 - mn1);
        li0 = li0 * al0 + rs0; li1 = li1 * al1 + rs1;
        mi0 = mn0; mi1 = mn1;
#pragma unroll
        for (int j = 0; j < 16; j++) {
            oa[j][0] *= al0; oa[j][1] *= al0;
            oa[j][2] *= al1; oa[j][3] *= al1;
        }

        // O += P V  (P fragments come straight from s[] registers)
#pragma unroll
        for (int kk = 0; kk < 4; kk++) {
            unsigned ah[4], alr[4];
            ah[0] = bfp(s[2 * kk][0], s[2 * kk][1]);
            ah[1] = bfp(s[2 * kk][2], s[2 * kk][3]);
            ah[2] = bfp(s[2 * kk + 1][0], s[2 * kk + 1][1]);
            ah[3] = bfp(s[2 * kk + 1][2], s[2 * kk + 1][3]);
            alr[0] = bfres(s[2 * kk][0], s[2 * kk][1], ah[0]);
            alr[1] = bfres(s[2 * kk][2], s[2 * kk][3], ah[1]);
            alr[2] = bfres(s[2 * kk + 1][0], s[2 * kk + 1][1], ah[2]);
            alr[3] = bfres(s[2 * kk + 1][2], s[2 * kk + 1][3], ah[3]);
#pragma unroll
            for (int j = 0; j < 16; j++) {
                int row = 8 * j + g;
                unsigned long long vh = *(const unsigned long long*)(Vh + row * VST + kk * 16 + lam * 4);
                unsigned long long vl = *(const unsigned long long*)(Vl + row * VST + kk * 16 + lam * 4);
                unsigned bh[2] = {(unsigned)vh, (unsigned)(vh >> 32)};
                unsigned bl[2] = {(unsigned)vl, (unsigned)(vl >> 32)};
                mmabf(oa[j], ah, bh);
                mmabf(oa[j], ah, bl);
                mmabf(oa[j], alr, bh);
            }
        }
        __syncthreads();
    }

    float i0 = 1.0f / li0, i1 = 1.0f / li1;
#pragma unroll
    for (int j = 0; j < 16; j++) {
        int c = h * HD + 8 * j + 2 * lam;
        *(float2*)(out + (size_t)(qr + g) * DM + c) = make_float2(oa[j][0] * i0, oa[j][1] * i0);
        *(float2*)(out + (size_t)(qr + g + 8) * DM + c) = make_float2(oa[j][2] * i1, oa[j][3] * i1);
    }
}

// ---- launch ----
extern "C" void kernel_launch(void* const* d_in, const int* in_sizes, int n_in,
                              void* d_out, int out_size)
{
    const float* h = (const float*)d_in[0];
    const float *Wq, *Wk, *Wv, *bq, *bk, *bv, *dq, *uq, *dk, *uk, *dv, *uv;

    if (in_sizes[2] < 10000) {
        Wq = (const float*)d_in[1];  bq = (const float*)d_in[2];
        Wk = (const float*)d_in[3];  bk = (const float*)d_in[4];
        Wv = (const float*)d_in[5];  bv = (const float*)d_in[6];
        dq = (const float*)d_in[7];  uq = (const float*)d_in[8];
        dk = (const float*)d_in[9];  uk = (const float*)d_in[10];
        dv = (const float*)d_in[11]; uv = (const float*)d_in[12];
    } else {
        Wq = (const float*)d_in[1];  Wk = (const float*)d_in[2];  Wv = (const float*)d_in[3];
        bq = (const float*)d_in[4];  bk = (const float*)d_in[5];  bv = (const float*)d_in[6];
        dq = (const float*)d_in[7];  dk = (const float*)d_in[8];  dv = (const float*)d_in[9];
        uq = (const float*)d_in[10]; uk = (const float*)d_in[11]; uv = (const float*)d_in[12];
    }
    const float* rmsq = (const float*)d_in[13];
    const float* rmsk = (const float*)d_in[14];
    const float* rc   = (const float*)d_in[15];
    const float* rs   = (const float*)d_in[16];
    float* out = (float*)d_out;

    cudaFuncSetAttribute(qkv_gemm_kernel, cudaFuncAttributeMaxDynamicSharedMemorySize, GEMM_SMEM_BYTES);
    cudaFuncSetAttribute(attn_kernel, cudaFuncAttributeMaxDynamicSharedMemorySize, ATT_SMEM_BYTES);

    split_hw_kernel<<<dim3(HWORDS / 256, 4), 256>>>(h, Wq, Wk, Wv);
    qkv_gemm_kernel<<<dim3(24, 24, 3), 256, GEMM_SMEM_BYTES>>>(bq, bk, bv);
    lora_down_kernel<<<dim3(32, 3), 256>>>(h, dq, dk, dv);
    lora_up_kernel<<<dim3(48, 16, 3), 256>>>(uq, uk, uv);
    rms_rope_kernel<<<dim3(3072, NH, 2), 128>>>(rmsq, rmsk, rc, rs);
    v_split_kernel<<<dim3(SQ / 64, NH), 256>>>();
    attn_kernel<<<dim3(24, NH), 256, ATT_SMEM_BYTES>>>(out);
}

// round 11
// speedup vs baseline: 3.1160x; 1.2583x over previous
#include <cuda_runtime.h>
#include <math.h>

#define SQ 3072
#define DM 3072
#define NH 24
#define HD 128
#define BLKROWS 2048
#define HWORDS (SQ * DM / 2)

__device__ float g_q[SQ * DM];
__device__ float g_k[SQ * DM];
__device__ float g_v[SQ * DM];
__device__ float g_t[3 * 1024 * 64];
// int8 2-digit operands for GEMM
__device__ char g_ad0[SQ * DM], g_ad1[SQ * DM];
__device__ char g_bd0[3][DM * DM], g_bd1[3][DM * DM];
__device__ float g_sa[SQ], g_sb[3][DM];
// bf16 hi/lo for attention (unchanged path)
__device__ unsigned g_qh[HWORDS], g_ql[HWORDS], g_kh[HWORDS], g_kl[HWORDS];
__device__ unsigned g_vth[HWORDS], g_vtl[HWORDS];

// ---- helpers ----
__device__ __forceinline__ unsigned long long pk2(float lo, float hi) {
    unsigned long long r;
    asm("mov.b64 %0, {%1, %2};" : "=l"(r) : "f"(lo), "f"(hi));
    return r;
}
__device__ __forceinline__ void upk2(unsigned long long v, float& lo, float& hi) {
    asm("mov.b64 {%0, %1}, %2;" : "=f"(lo), "=f"(hi) : "l"(v));
}
__device__ __forceinline__ void fma2(unsigned long long& d, unsigned long long a, unsigned long long b) {
    asm("fma.rn.f32x2 %0, %1, %2, %0;" : "+l"(d) : "l"(a), "l"(b));
}
__device__ __forceinline__ unsigned bfp(float x0, float x1) {
    unsigned r;
    asm("cvt.rn.bf16x2.f32 %0, %1, %2;" : "=r"(r) : "f"(x1), "f"(x0));
    return r;
}
__device__ __forceinline__ float bflo(unsigned u) { return __uint_as_float(u << 16); }
__device__ __forceinline__ float bfhi(unsigned u) { return __uint_as_float(u & 0xffff0000u); }
__device__ __forceinline__ unsigned bfres(float x0, float x1, unsigned hi) {
    return bfp(x0 - bflo(hi), x1 - bfhi(hi));
}
__device__ __forceinline__ void mmabf(float* c, const unsigned* a, const unsigned* b) {
    asm volatile(
        "mma.sync.aligned.m16n8k16.row.col.f32.bf16.bf16.f32 "
        "{%0,%1,%2,%3}, {%4,%5,%6,%7}, {%8,%9}, {%0,%1,%2,%3};\n"
        : "+f"(c[0]), "+f"(c[1]), "+f"(c[2]), "+f"(c[3])
        : "r"(a[0]), "r"(a[1]), "r"(a[2]), "r"(a[3]), "r"(b[0]), "r"(b[1]));
}
__device__ __forceinline__ void mmai8(int* c, const unsigned* a, const unsigned* b) {
    asm volatile(
        "mma.sync.aligned.m16n8k32.row.col.s32.s8.s8.s32 "
        "{%0,%1,%2,%3}, {%4,%5,%6,%7}, {%8,%9}, {%0,%1,%2,%3};\n"
        : "+r"(c[0]), "+r"(c[1]), "+r"(c[2]), "+r"(c[3])
        : "r"(a[0]), "r"(a[1]), "r"(a[2]), "r"(a[3]), "r"(b[0]), "r"(b[1]));
}
__device__ __forceinline__ void cpa(unsigned dst, const void* src) {
    asm volatile("cp.async.cg.shared.global [%0], [%1], 16;\n" :: "r"(dst), "l"(src));
}
__device__ __forceinline__ void cp_commit() { asm volatile("cp.async.commit_group;\n"); }
template <int N> __device__ __forceinline__ void cp_wait() {
    asm volatile("cp.async.wait_group %0;\n" :: "n"(N));
}
__device__ __forceinline__ unsigned s2u(const void* p) {
    return (unsigned)__cvta_generic_to_shared(p);
}

// ---- 0) digitize h + W rows into 2x int8 digits with row scales ----
// phys byte q in 8B group t of a 32-elem chunk holds logical
// k = (q<4) ? 4t+q : 16+4t+(q-4)  -> one LDS.64 yields (frag0, frag1) regs.
__global__ __launch_bounds__(256) void digitize_kernel(
    const float* __restrict__ h, const float* __restrict__ Wq,
    const float* __restrict__ Wk, const float* __restrict__ Wv)
{
    const int a = blockIdx.y;
    const int row = blockIdx.x;
    const float* src = ((a == 0) ? h : (a == 1) ? Wq : (a == 2) ? Wk : Wv) + (size_t)row * DM;
    char* d0 = (a == 0) ? g_ad0 : g_bd0[a - 1];
    char* d1 = (a == 0) ? g_ad1 : g_bd1[a - 1];
    float* sc = (a == 0) ? g_sa : g_sb[a - 1];

    const int tid = threadIdx.x;
    float mx = 0.f;
    for (int i = tid; i < DM; i += 256) mx = fmaxf(mx, fabsf(src[i]));
#pragma unroll
    for (int o = 16; o; o >>= 1) mx = fmaxf(mx, __shfl_xor_sync(0xffffffffu, mx, o));
    __shared__ float red[8];
    if ((tid & 31) == 0) red[tid >> 5] = mx;
    __syncthreads();
    mx = red[0];
#pragma unroll
    for (int i = 1; i < 8; i++) mx = fmaxf(mx, red[i]);
    float S = fmaxf(mx * 1.02f, 1e-30f);
    if (tid == 0) sc[row] = S * 0.0078125f;  // S/128
    const float inv = 128.0f / S;

    for (int gi = tid; gi < DM / 8; gi += 256) {
        int c = gi >> 2, t = gi & 3;
        int kb = c * 32 + 4 * t;
        unsigned long long p0 = 0, p1 = 0;
#pragma unroll
        for (int q = 0; q < 8; q++) {
            int k = (q < 4) ? kb + q : kb + 12 + q;
            float x = src[k] * inv;
            int m0 = __float2int_rn(x);
            int m1 = __float2int_rn((x - (float)m0) * 128.0f);
            p0 |= (unsigned long long)((unsigned)m0 & 0xffu) << (8 * q);
            p1 |= (unsigned long long)((unsigned)m1 & 0xffu) << (8 * q);
        }
        *(unsigned long long*)(d0 + (size_t)row * DM + gi * 8) = p0;
        *(unsigned long long*)(d1 + (size_t)row * DM + gi * 8) = p1;
    }
}

// ---- 1) QKV GEMM via int8 2-digit mma.sync: C = h @ W.T + b ----
// block 128x128, BK=64, 16 warps (4x4, warp tile 32x32), 3-stage cp.async.
// 64 int accumulators/thread (low reg pressure).
#define RS 80
#define TILEB (128 * RS)
#define BUFB (4 * TILEB)
#define NBUF 3
#define GEMM_DSMEM (NBUF * BUFB)
#define NTIL 48

__global__ __launch_bounds__(512) void qkv_gemm_kernel(
    const float* __restrict__ bq, const float* __restrict__ bk, const float* __restrict__ bv)
{
    extern __shared__ char dsm[];
    const int z = blockIdx.z;
    const char* Bd0 = g_bd0[z];
    const char* Bd1 = g_bd1[z];
    const float* bias = (z == 0) ? bq : (z == 1) ? bk : bv;
    const float* sB = g_sb[z];
    float* C = (z == 0) ? g_q : (z == 1) ? g_k : g_v;

    const int tid = threadIdx.x;
    const int lane = tid & 31;
    const int warp = tid >> 5;       // 0..15
    const int g = lane >> 2;
    const int lam = lane & 3;
    const int mw = warp >> 2;        // 0..3 (32 rows each)
    const int nw = warp & 3;         // 0..3 (32 cols each)
    const int m0 = blockIdx.y * 128;
    const int n0 = blockIdx.x * 128;
    unsigned sbase = s2u(dsm);

    int P0[2][4][4], P1[2][4][4];
#pragma unroll
    for (int i = 0; i < 2; i++)
#pragma unroll
        for (int j = 0; j < 4; j++)
#pragma unroll
            for (int r = 0; r < 4; r++) { P0[i][j][r] = 0; P1[i][j][r] = 0; }

    auto issue_load = [&](int t, int buf) {
        int k0 = t * 64;
#pragma unroll
        for (int j = 0; j < 4; j++) {
            int cid = tid + 512 * j;
            int arr = cid >> 9;
            int c2 = cid & 511, row = c2 >> 2, ch = c2 & 3;
            const char* sp = (arr == 0) ? g_ad0 : (arr == 1) ? g_ad1 : (arr == 2) ? Bd0 : Bd1;
            int grow = ((arr < 2) ? m0 : n0) + row;
            cpa(sbase + (unsigned)(buf * BUFB + arr * TILEB + row * RS + ch * 16),
                sp + (size_t)grow * DM + k0 + ch * 16);
        }
    };

    issue_load(0, 0); cp_commit();
    issue_load(1, 1); cp_commit();
    issue_load(2, 2); cp_commit();

    for (int it = 0; it < NTIL; it++) {
        cp_wait<2>();
        __syncthreads();
        const char* bb = dsm + (it % 3) * BUFB;

#pragma unroll
        for (int kt = 0; kt < 2; kt++) {
            unsigned Af[2][2][4], Bf[2][4][2];
#pragma unroll
            for (int i = 0; i < 2; i++) {
                int r0 = mw * 32 + 16 * i + g;
#pragma unroll
                for (int dg = 0; dg < 2; dg++) {
                    unsigned long long v0 = *(const unsigned long long*)(bb + dg * TILEB + r0 * RS + kt * 32 + 8 * lam);
                    unsigned long long v1 = *(const unsigned long long*)(bb + dg * TILEB + (r0 + 8) * RS + kt * 32 + 8 * lam);
                    Af[dg][i][0] = (unsigned)v0; Af[dg][i][2] = (unsigned)(v0 >> 32);
                    Af[dg][i][1] = (unsigned)v1; Af[dg][i][3] = (unsigned)(v1 >> 32);
                }
            }
#pragma unroll
            for (int j = 0; j < 4; j++) {
                int n = nw * 32 + 8 * j + g;
#pragma unroll
                for (int dg = 0; dg < 2; dg++) {
                    unsigned long long v = *(const unsigned long long*)(bb + (2 + dg) * TILEB + n * RS + kt * 32 + 8 * lam);
                    Bf[dg][j][0] = (unsigned)v; Bf[dg][j][1] = (unsigned)(v >> 32);
                }
            }
#pragma unroll
            for (int i = 0; i < 2; i++)
#pragma unroll
                for (int j = 0; j < 4; j++) {
                    mmai8(P0[i][j], Af[0][i], Bf[0][j]);
                    mmai8(P1[i][j], Af[0][i], Bf[1][j]);
                    mmai8(P1[i][j], Af[1][i], Bf[0][j]);
                }
        }
        __syncthreads();
        if (it + 3 < NTIL) issue_load(it + 3, (it + 3) % 3);
        cp_commit();
    }

#pragma unroll
    for (int j = 0; j < 4; j++) {
        int col = n0 + nw * 32 + 8 * j + 2 * lam;
        float sb0 = sB[col], sb1 = sB[col + 1];
        float b0 = bias[col], b1 = bias[col + 1];
#pragma unroll
        for (int i = 0; i < 2; i++) {
            int r0 = m0 + mw * 32 + 16 * i + g;
            float sa0 = g_sa[r0], sa1 = g_sa[r0 + 8];
            float c00 = sa0 * sb0 * ((float)P0[i][j][0] + 0.0078125f * (float)P1[i][j][0]) + b0;
            float c01 = sa0 * sb1 * ((float)P0[i][j][1] + 0.0078125f * (float)P1[i][j][1]) + b1;
            float c10 = sa1 * sb0 * ((float)P0[i][j][2] + 0.0078125f * (float)P1[i][j][2]) + b0;
            float c11 = sa1 * sb1 * ((float)P0[i][j][3] + 0.0078125f * (float)P1[i][j][3]) + b1;
            *(float2*)(C + (size_t)r0 * DM + col) = make_float2(c00, c01);
            *(float2*)(C + (size_t)(r0 + 8) * DM + col) = make_float2(c10, c11);
        }
    }
}

// ---- 2) LoRA down ----
__global__ __launch_bounds__(256) void lora_down_kernel(
    const float* __restrict__ h,
    const float* __restrict__ dq, const float* __restrict__ dk, const float* __restrict__ dv)
{
    const int x = blockIdx.y;
    const float* __restrict__ D = (x == 0) ? dq : (x == 1) ? dk : dv;
    const int i0 = blockIdx.x * 32;
    __shared__ float hs[32][65];
    __shared__ float ds[64][65];
    const int tid = threadIdx.x;
    const int r = tid & 31;
    const int c0 = (tid >> 5) * 8;
    float acc[8] = {0.f, 0.f, 0.f, 0.f, 0.f, 0.f, 0.f, 0.f};

    for (int k0 = 0; k0 < DM; k0 += 64) {
#pragma unroll
        for (int t = 0; t < 8; t++) {
            int idx = tid + t * 256;
            hs[idx >> 6][idx & 63] = h[(size_t)(BLKROWS + i0 + (idx >> 6)) * DM + k0 + (idx & 63)];
        }
#pragma unroll
        for (int t = 0; t < 16; t++) {
            int idx = tid + t * 256;
            ds[idx >> 6][idx & 63] = D[(size_t)(idx >> 6) * DM + k0 + (idx & 63)];
        }
        __syncthreads();
#pragma unroll 8
        for (int kk = 0; kk < 64; kk++) {
            float a = hs[r][kk];
#pragma unroll
            for (int j = 0; j < 8; j++) acc[j] += a * ds[c0 + j][kk];
        }
        __syncthreads();
    }
#pragma unroll
    for (int j = 0; j < 8; j++)
        g_t[x * 65536 + (i0 + r) * 64 + c0 + j] = acc[j];
}

// ---- 3) LoRA up ----
__global__ __launch_bounds__(256) void lora_up_kernel(
    const float* __restrict__ uq, const float* __restrict__ uk, const float* __restrict__ uv)
{
    const int x = blockIdx.z;
    const float* __restrict__ U = (x == 0) ? uq : (x == 1) ? uk : uv;
    float* C = (x == 0) ? g_q : (x == 1) ? g_k : g_v;
    const int n0 = blockIdx.x * 64;
    const int i0 = blockIdx.y * 64;
    __shared__ float ts[64][68];
    __shared__ float uss[64][68];
    const int tid = threadIdx.x;
#pragma unroll
    for (int t = 0; t < 16; t++) {
        int idx = tid + t * 256;
        int ii = idx >> 6, rr = idx & 63;
        ts[rr][ii] = g_t[x * 65536 + (i0 + ii) * 64 + rr];
        uss[rr][ii] = U[(size_t)(n0 + ii) * 64 + rr];
    }
    __syncthreads();
    const int tm = tid >> 4, tn = tid & 15;
    unsigned long long acc[4][2];
#pragma unroll
    for (int i = 0; i < 4; i++) { acc[i][0] = 0ull; acc[i][1] = 0ull; }
#pragma unroll 8
    for (int rr = 0; rr < 64; rr++) {
        float4 a = *(const float4*)&ts[rr][tm * 4];
        ulonglong2 b = *(const ulonglong2*)&uss[rr][tn * 4];
        float af[4] = {a.x, a.y, a.z, a.w};
#pragma unroll
        for (int i = 0; i < 4; i++) {
            unsigned long long a2 = pk2(af[i], af[i]);
            fma2(acc[i][0], a2, b.x);
            fma2(acc[i][1], a2, b.y);
        }
    }
#pragma unroll
    for (int i = 0; i < 4; i++) {
        float c0, c1, c2, c3;
        upk2(acc[i][0], c0, c1);
        upk2(acc[i][1], c2, c3);
        float* dst = C + (size_t)(BLKROWS + i0 + tm * 4 + i) * DM + n0 + tn * 4;
        float4 old = *(float4*)dst;
        old.x += c0; old.y += c1; old.z += c2; old.w += c3;
        *(float4*)dst = old;
    }
}

// ---- 4) RMSNorm + RoPE -> bf16 hi/lo split (k16-permuted) ----
__global__ __launch_bounds__(128) void rms_rope_kernel(
    const float* __restrict__ wq, const float* __restrict__ wk,
    const float* __restrict__ cosb, const float* __restrict__ sinb)
{
    const int s = blockIdx.x;
    const int hh = blockIdx.y;
    const int qk = blockIdx.z;
    const int d = threadIdx.x;
    const float* buf = qk ? g_k : g_q;
    const float* w = qk ? wk : wq;
    unsigned* oh = qk ? g_kh : g_qh;
    unsigned* ol = qk ? g_kl : g_ql;

    size_t idx = (size_t)s * DM + hh * HD + d;
    float x = buf[idx];
    float v = x * x;
#pragma unroll
    for (int o = 16; o; o >>= 1) v += __shfl_xor_sync(0xffffffffu, v, o);
    __shared__ float red[4];
    if ((d & 31) == 0) red[d >> 5] = v;
    __syncthreads();
    float tot = red[0] + red[1] + red[2] + red[3];
    float y = x * rsqrtf(tot * (1.0f / 128.0f) + 1e-6f) * w[d];
    float partner = __shfl_xor_sync(0xffffffffu, y, 1);
    float xr = (d & 1) ? partner : -partner;
    float f = y * cosb[s * HD + d] + xr * sinb[s * HD + d];
    if (!qk) f *= 0.08838834764831845f;

    float mate = __shfl_xor_sync(0xffffffffu, f, 1);
    if (!(d & 1)) {
        int l = (d & 15) >> 1;
        int p = (l < 4) ? 2 * l : 2 * (l - 4) + 1;
        size_t wo = ((size_t)s * DM + hh * HD) / 2 + (d >> 4) * 8 + p;
        unsigned hi = bfp(f, mate);
        oh[wo] = hi;
        ol[wo] = bfres(f, mate, hi);
    }
}

// ---- 4b) V split + transpose ----
__global__ __launch_bounds__(256) void v_split_kernel()
{
    __shared__ float vs[64][129];
    const int s0 = blockIdx.x * 64;
    const int hh = blockIdx.y;
    const int tid = threadIdx.x;
    for (int t = tid; t < 64 * 128; t += 256) {
        int r = t >> 7, d = t & 127;
        vs[r][d] = g_v[(size_t)(s0 + r) * DM + hh * HD + d];
    }
    __syncthreads();
    for (int t = tid; t < 128 * 32; t += 256) {
        int d = t >> 5, wloc = t & 31;
        int p = wloc & 7;
        int l = (p & 1) ? (p >> 1) + 4 : (p >> 1);
        int n = (wloc & ~7) * 2 + 2 * l;
        float x0 = vs[n][d], x1 = vs[n + 1][d];
        unsigned hi = bfp(x0, x1);
        size_t o = ((size_t)hh * HD + d) * (SQ / 2) + s0 / 2 + wloc;
        g_vth[o] = hi;
        g_vtl[o] = bfres(x0, x1, hi);
    }
}

// ---- 5) Flash attention (bf16 3-term mma.sync) ----
#define KST 136
#define VST 72
#define ATT_SMEM_BYTES (2 * (2 * 64 * KST + 2 * 128 * VST) * 2)

__global__ __launch_bounds__(256) void attn_kernel(float* __restrict__ out)
{
    extern __shared__ unsigned short as[];
    const int BUFU = 2 * 64 * KST + 2 * 128 * VST;
    const int m0 = blockIdx.x * 128;
    const int h = blockIdx.y;
    const int tid = threadIdx.x;
    const int lane = tid & 31;
    const int warp = tid >> 5;
    const int g = lane >> 2;
    const int lam = lane & 3;
    const int qr = m0 + warp * 16;
    unsigned sbase = s2u(as);

    unsigned qfh[8][4], qfl[8][4];
    {
        size_t b0 = ((size_t)(qr + g) * DM + h * HD) / 2;
        size_t b1 = ((size_t)(qr + g + 8) * DM + h * HD) / 2;
#pragma unroll
        for (int kt = 0; kt < 8; kt++) {
            unsigned long long h0 = *(const unsigned long long*)(g_qh + b0 + kt * 8 + 2 * lam);
            unsigned long long h1 = *(const unsigned long long*)(g_qh + b1 + kt * 8 + 2 * lam);
            unsigned long long l0 = *(const unsigned long long*)(g_ql + b0 + kt * 8 + 2 * lam);
            unsigned long long l1 = *(const unsigned long long*)(g_ql + b1 + kt * 8 + 2 * lam);
            qfh[kt][0] = (unsigned)h0; qfh[kt][2] = (unsigned)(h0 >> 32);
            qfh[kt][1] = (unsigned)h1; qfh[kt][3] = (unsigned)(h1 >> 32);
            qfl[kt][0] = (unsigned)l0; qfl[kt][2] = (unsigned)(l0 >> 32);
            qfl[kt][1] = (unsigned)l1; qfl[kt][3] = (unsigned)(l1 >> 32);
        }
    }

    float oa[16][4];
#pragma unroll
    for (int j = 0; j < 16; j++)
#pragma unroll
        for (int r = 0; r < 4; r++) oa[j][r] = 0.f;
    float mi0 = -1e30f, mi1 = -1e30f, li0 = 0.f, li1 = 0.f;

    const int n_start = (m0 >= BLKROWS) ? BLKROWS : 0;
    const int NTK = (SQ - n_start) / 64;

    auto issue = [&](int ti, int b) {
        int n0 = n_start + ti * 64;
        unsigned d0 = sbase + (unsigned)(b * BUFU * 2);
#pragma unroll
        for (int j = 0; j < 8; j++) {
            int cid = tid + 256 * j;
            int hl = cid >> 10, c2 = cid & 1023;
            int row = c2 >> 4, c = c2 & 15;
            const unsigned* src = (hl ? g_kl : g_kh) + ((size_t)(n0 + row) * DM + h * HD) / 2 + c * 4;
            cpa(d0 + (unsigned)((hl * 64 * KST + row * KST) * 2 + c * 16), src);
        }
        unsigned dv = d0 + (unsigned)(2 * 64 * KST * 2);
#pragma unroll
        for (int j = 0; j < 8; j++) {
            int cid = tid + 256 * j;
            int hl = cid >> 10, c2 = cid & 1023;
            int row = c2 >> 3, c = c2 & 7;
            const unsigned* src = (hl ? g_vtl : g_vth) + ((size_t)h * HD + row) * (SQ / 2) + n0 / 2 + c * 4;
            cpa(dv + (unsigned)((hl * 128 * VST + row * VST) * 2 + c * 16), src);
        }
    };

    issue(0, 0); cp_commit();

    for (int ti = 0; ti < NTK; ti++) {
        if (ti + 1 < NTK) { issue(ti + 1, (ti + 1) & 1); cp_commit(); cp_wait<1>(); }
        else cp_wait<0>();
        __syncthreads();
        const unsigned short* bb = as + (ti & 1) * BUFU;
        const unsigned short* Kh = bb;
        const unsigned short* Kl = bb + 64 * KST;
        const unsigned short* Vh = bb + 2 * 64 * KST;
        const unsigned short* Vl = Vh + 128 * VST;

        float s[8][4];
#pragma unroll
        for (int j = 0; j < 8; j++)
#pragma unroll
            for (int r = 0; r < 4; r++) s[j][r] = 0.f;
#pragma unroll
        for (int kt = 0; kt < 8; kt++) {
#pragma unroll
            for (int j = 0; j < 8; j++) {
                int row = 8 * j + g;
                unsigned long long vh = *(const unsigned long long*)(Kh + row * KST + kt * 16 + lam * 4);
                unsigned long long vl = *(const unsigned long long*)(Kl + row * KST + kt * 16 + lam * 4);
                unsigned bh[2] = {(unsigned)vh, (unsigned)(vh >> 32)};
                unsigned bl[2] = {(unsigned)vl, (unsigned)(vl >> 32)};
                mmabf(s[j], qfh[kt], bh);
                mmabf(s[j], qfh[kt], bl);
                mmabf(s[j], qfl[kt], bh);
            }
        }

        float mx0 = -1e30f, mx1 = -1e30f;
#pragma unroll
        for (int j = 0; j < 8; j++) {
            mx0 = fmaxf(mx0, fmaxf(s[j][0], s[j][1]));
            mx1 = fmaxf(mx1, fmaxf(s[j][2], s[j][3]));
        }
        mx0 = fmaxf(mx0, __shfl_xor_sync(0xffffffffu, mx0, 1));
        mx0 = fmaxf(mx0, __shfl_xor_sync(0xffffffffu, mx0, 2));
        mx1 = fmaxf(mx1, __shfl_xor_sync(0xffffffffu, mx1, 1));
        mx1 = fmaxf(mx1, __shfl_xor_sync(0xffffffffu, mx1, 2));
        float mn0 = fmaxf(mi0, mx0), mn1 = fmaxf(mi1, mx1);
        float rs0 = 0.f, rs1 = 0.f;
#pragma unroll
        for (int j = 0; j < 8; j++) {
            s[j][0] = __expf(s[j][0] - mn0); rs0 += s[j][0];
            s[j][1] = __expf(s[j][1] - mn0); rs0 += s[j][1];
            s[j][2] = __expf(s[j][2] - mn1); rs1 += s[j][2];
            s[j][3] = __expf(s[j][3] - mn1); rs1 += s[j][3];
        }
        rs0 += __shfl_xor_sync(0xffffffffu, rs0, 1);
        rs0 += __shfl_xor_sync(0xffffffffu, rs0, 2);
        rs1 += __shfl_xor_sync(0xffffffffu, rs1, 1);
        rs1 += __shfl_xor_sync(0xffffffffu, rs1, 2);
        float al0 = __expf(mi0 - mn0), al1 = __expf(mi1 - mn1);
        li0 = li0 * al0 + rs0; li1 = li1 * al1 + rs1;
        mi0 = mn0; mi1 = mn1;
#pragma unroll
        for (int j = 0; j < 16; j++) {
            oa[j][0] *= al0; oa[j][1] *= al0;
            oa[j][2] *= al1; oa[j][3] *= al1;
        }

#pragma unroll
        for (int kk = 0; kk < 4; kk++) {
            unsigned ah[4], alr[4];
            ah[0] = bfp(s[2 * kk][0], s[2 * kk][1]);
            ah[1] = bfp(s[2 * kk][2], s[2 * kk][3]);
            ah[2] = bfp(s[2 * kk + 1][0], s[2 * kk + 1][1]);
            ah[3] = bfp(s[2 * kk + 1][2], s[2 * kk + 1][3]);
            alr[0] = bfres(s[2 * kk][0], s[2 * kk][1], ah[0]);
            alr[1] = bfres(s[2 * kk][2], s[2 * kk][3], ah[1]);
            alr[2] = bfres(s[2 * kk + 1][0], s[2 * kk + 1][1], ah[2]);
            alr[3] = bfres(s[2 * kk + 1][2], s[2 * kk + 1][3], ah[3]);
#pragma unroll
            for (int j = 0; j < 16; j++) {
                int row = 8 * j + g;
                unsigned long long vh = *(const unsigned long long*)(Vh + row * VST + kk * 16 + lam * 4);
                unsigned long long vl = *(const unsigned long long*)(Vl + row * VST + kk * 16 + lam * 4);
                unsigned bh[2] = {(unsigned)vh, (unsigned)(vh >> 32)};
                unsigned bl[2] = {(unsigned)vl, (unsigned)(vl >> 32)};
                mmabf(oa[j], ah, bh);
                mmabf(oa[j], ah, bl);
                mmabf(oa[j], alr, bh);
            }
        }
        __syncthreads();
    }

    float i0 = 1.0f / li0, i1 = 1.0f / li1;
#pragma unroll
    for (int j = 0; j < 16; j++) {
        int c = h * HD + 8 * j + 2 * lam;
        *(float2*)(out + (size_t)(qr + g) * DM + c) = make_float2(oa[j][0] * i0, oa[j][1] * i0);
        *(float2*)(out + (size_t)(qr + g + 8) * DM + c) = make_float2(oa[j][2] * i1, oa[j][3] * i1);
    }
}

// ---- launch ----
extern "C" void kernel_launch(void* const* d_in, const int* in_sizes, int n_in,
                              void* d_out, int out_size)
{
    const float* h = (const float*)d_in[0];
    const float *Wq, *Wk, *Wv, *bq, *bk, *bv, *dq, *uq, *dk, *uk, *dv, *uv;

    if (in_sizes[2] < 10000) {
        Wq = (const float*)d_in[1];  bq = (const float*)d_in[2];
        Wk = (const float*)d_in[3];  bk = (const float*)d_in[4];
        Wv = (const float*)d_in[5];  bv = (const float*)d_in[6];
        dq = (const float*)d_in[7];  uq = (const float*)d_in[8];
        dk = (const float*)d_in[9];  uk = (const float*)d_in[10];
        dv = (const float*)d_in[11]; uv = (const float*)d_in[12];
    } else {
        Wq = (const float*)d_in[1];  Wk = (const float*)d_in[2];  Wv = (const float*)d_in[3];
        bq = (const float*)d_in[4];  bk = (const float*)d_in[5];  bv = (const float*)d_in[6];
        dq = (const float*)d_in[7];  dk = (const float*)d_in[8];  dv = (const float*)d_in[9];
        uq = (const float*)d_in[10]; uk = (const float*)d_in[11]; uv = (const float*)d_in[12];
    }
    const float* rmsq = (const float*)d_in[13];
    const float* rmsk = (const float*)d_in[14];
    const float* rc   = (const float*)d_in[15];
    const float* rs   = (const float*)d_in[16];
    float* out = (float*)d_out;

    cudaFuncSetAttribute(qkv_gemm_kernel, cudaFuncAttributeMaxDynamicSharedMemorySize, GEMM_DSMEM);
    cudaFuncSetAttribute(attn_kernel, cudaFuncAttributeMaxDynamicSharedMemorySize, ATT_SMEM_BYTES);

    digitize_kernel<<<dim3(DM, 4), 256>>>(h, Wq, Wk, Wv);
    qkv_gemm_kernel<<<dim3(24, 24, 3), 512, GEMM_DSMEM>>>(bq, bk, bv);
    lora_down_kernel<<<dim3(32, 3), 256>>>(h, dq, dk, dv);
    lora_up_kernel<<<dim3(48, 16, 3), 256>>>(uq, uk, uv);
    rms_rope_kernel<<<dim3(3072, NH, 2), 128>>>(rmsq, rmsk, rc, rs);
    v_split_kernel<<<dim3(SQ / 64, NH), 256>>>();
    attn_kernel<<<dim3(24, NH), 256, ATT_SMEM_BYTES>>>(out);
}